// round 10
// baseline (speedup 1.0000x reference)
#include <cuda_runtime.h>
#include <math.h>

#define BROWS 2048
#define NCLS  1000
#define KDIM  2048
#define NSTEPS 100

#define LRc   0.1f
#define B1c   0.9f
#define B2c   0.999f
#define EPSc  1e-8f
#define BETAc 5.0f
#define TAUc  6.0f
#define PI_F  3.14159274101257324f   // float(np.pi)

// ---------------- device scratch (static, no allocation) ----------------
__device__ float  g_z[BROWS * NCLS];
__device__ float2 g_mv[BROWS * NCLS];     // interleaved Adam m,v
__device__ float  g_T[BROWS * BROWS];     // l_trg, class-slot layout
__device__ float  g_topz[BROWS];
__device__ float  g_topu2[2][BROWS];      // double-buffered topu (slot order)
__device__ float  g_rowmax[BROWS];
__device__ float  g_sumexp[BROWS];
__device__ int    g_rowarg[BROWS];
__device__ float  g_ptrg[BROWS];
__device__ int    g_y[BROWS];
__device__ int    g_allowed[NCLS];
__device__ unsigned int g_maskw[32];      // allowed bitmask (1000 bits)
__device__ int    g_count[NCLS];
__device__ int    g_start[NCLS];
__device__ int    g_cursor[NCLS];
__device__ int    g_member[BROWS];        // row j, sorted by class
__device__ int    g_classOf[BROWS];       // class of slot k
__device__ int    g_slotOfRow[BROWS];     // inverse of g_member
__device__ int    g_istar;
__device__ int    g_cstar;
__device__ float  g_rmaxstar;
__device__ float  g_sumexpstar;
__device__ float  g_coef;

// ---------------- GEMM: z = x @ W + b (UNCHANGED from passing R9) ----------------
__global__ void __launch_bounds__(256)
gemm_kernel(const float* __restrict__ x,
            const float* __restrict__ W,
            const float* __restrict__ bias) {
    __shared__ float As[128][16];
    __shared__ float Bs[16][64];
    const int tid = threadIdx.x;
    const int tx = tid & 15;
    const int ty = tid >> 4;
    const int row0 = blockIdx.y * 128;
    const int col0 = blockIdx.x * 64;

    const int bk = tid >> 4;
    const int bn = (tid & 15) * 4;

    float acc[8][4];
#pragma unroll
    for (int i = 0; i < 8; ++i)
#pragma unroll
        for (int j = 0; j < 4; ++j) acc[i][j] = 0.f;

    for (int k0 = 0; k0 < KDIM; k0 += 16) {
#pragma unroll
        for (int q = 0; q < 2; ++q) {
            int idx = tid * 2 + q;
            int m  = idx >> 2;
            int kk = (idx & 3) * 4;
            float4 xa = *reinterpret_cast<const float4*>(
                &x[(size_t)(row0 + m) * KDIM + k0 + kk]);
            *reinterpret_cast<float4*>(&As[m][kk]) = xa;
        }
        {
            int n = col0 + bn;
            float4 wb;
            if (n + 3 < NCLS) {
                wb = *reinterpret_cast<const float4*>(&W[(size_t)(k0 + bk) * NCLS + n]);
            } else {
                wb = make_float4(0.f, 0.f, 0.f, 0.f);
            }
            *reinterpret_cast<float4*>(&Bs[bk][bn]) = wb;
        }
        __syncthreads();
#pragma unroll
        for (int kk = 0; kk < 16; ++kk) {
            float a[8];
#pragma unroll
            for (int i = 0; i < 8; ++i) a[i] = As[ty * 8 + i][kk];
            float4 bb = *reinterpret_cast<const float4*>(&Bs[kk][tx * 4]);
#pragma unroll
            for (int i = 0; i < 8; ++i) {
                acc[i][0] = fmaf(a[i], bb.x, acc[i][0]);
                acc[i][1] = fmaf(a[i], bb.y, acc[i][1]);
                acc[i][2] = fmaf(a[i], bb.z, acc[i][2]);
                acc[i][3] = fmaf(a[i], bb.w, acc[i][3]);
            }
        }
        __syncthreads();
    }
#pragma unroll
    for (int i = 0; i < 8; ++i) {
        int row = row0 + ty * 8 + i;
#pragma unroll
        for (int j = 0; j < 4; ++j) {
            int col = col0 + tx * 4 + j;
            if (col < NCLS) g_z[(size_t)row * NCLS + col] = acc[i][j] + bias[col];
        }
    }
}

// ---------------- setup kernels (identical arithmetic to R1) ----------------
__global__ void init_class_kernel() {
    int c = blockIdx.x * blockDim.x + threadIdx.x;
    if (c < NCLS) { g_allowed[c] = 1; g_count[c] = 0; g_cursor[c] = 0; }
}

__global__ void statsz_kernel() {
    int row = blockIdx.x;
    const float* a = g_z + (size_t)row * NCLS;
    int tid = threadIdx.x;

    float va[4];
    int   nv = 0;
    float vmax = -3.402823466e38f;
    int   vidx = NCLS;
    for (int c = tid; c < NCLS; c += 256) {
        float v = a[c];
        va[nv++] = v;
        if (v > vmax) { vmax = v; vidx = c; }
    }
    __shared__ float smax[256];
    __shared__ int   sidx[256];
    __shared__ float ssum[256];
    smax[tid] = vmax; sidx[tid] = vidx;
    __syncthreads();
    for (int s = 128; s > 0; s >>= 1) {
        if (tid < s) {
            float ov = smax[tid + s]; int oi = sidx[tid + s];
            if (ov > smax[tid] || (ov == smax[tid] && oi < sidx[tid])) { smax[tid] = ov; sidx[tid] = oi; }
        }
        __syncthreads();
    }
    float rmax = smax[0];
    float se = 0.f;
    for (int q = 0; q < nv; ++q) se += expf(va[q] - rmax);
    ssum[tid] = se;
    __syncthreads();
    for (int s = 128; s > 0; s >>= 1) {
        if (tid < s) ssum[tid] += ssum[tid + s];
        __syncthreads();
    }
    if (tid == 0) {
        g_rowmax[row] = rmax;
        g_sumexp[row] = ssum[0];
        g_rowarg[row] = sidx[0];
        g_y[row] = sidx[0];
        g_ptrg[row] = 1.0f / ssum[0];
    }
}

__global__ void mark_kernel() {
    int i = blockIdx.x * blockDim.x + threadIdx.x;
    if (i < BROWS) {
        int c = g_y[i];
        g_allowed[c] = 0;
        atomicAdd(&g_count[c], 1);
    }
}

__global__ void scan_kernel() {
    if (threadIdx.x == 0 && blockIdx.x == 0) {
        int s = 0;
        for (int c = 0; c < NCLS; ++c) { g_start[c] = s; s += g_count[c]; }
    }
}

__global__ void scatter_kernel() {
    int i = blockIdx.x * blockDim.x + threadIdx.x;
    if (i < BROWS) {
        int c = g_y[i];
        int pos = g_start[c] + atomicAdd(&g_cursor[c], 1);
        g_member[pos]    = i;
        g_classOf[pos]   = c;
        g_slotOfRow[i]   = pos;
    }
}

__global__ void maskw_kernel() {
    int w = threadIdx.x;   // 32 threads
    unsigned int m = 0;
    for (int b = 0; b < 32; ++b) {
        int c = w * 32 + b;
        if (c < NCLS && g_allowed[c]) m |= (1u << b);
    }
    g_maskw[w] = m;
}

// masked top over z + fill initial topu buffer 0 (slot order)
__global__ void topz_kernel() {
    int row = blockIdx.x;
    int tid = threadIdx.x;
    float tmax = -1000.0f;
    for (int c = tid; c < NCLS; c += 256) {
        if (g_allowed[c]) {
            float v = g_z[(size_t)row * NCLS + c];
            if (v > tmax) tmax = v;
        }
    }
    __shared__ float st[256];
    st[tid] = tmax;
    __syncthreads();
    for (int s = 128; s > 0; s >>= 1) {
        if (tid < s) { float o = st[tid + s]; if (o > st[tid]) st[tid] = o; }
        __syncthreads();
    }
    if (tid == 0) {
        g_topz[row] = st[0];
        g_topu2[0][g_slotOfRow[row]] = st[0];
    }
}

__global__ void computeT_kernel() {
    int idx = blockIdx.x * blockDim.x + threadIdx.x;
    int i = idx >> 11;
    int k = idx & 2047;
    int c = g_classOf[k];
    int j = g_member[k];
    float lorg = g_z[(size_t)i * NCLS + c] - g_topz[j];
    float latr = (floorf(lorg / TAUc) + 0.5f) * TAUc;
    float arg  = PI_F * (1.0f - 2.0f * (lorg - latr) / TAUc);
    g_T[idx] = lorg - TAUc * sinf(arg);
}

__global__ void init_u_kernel(float* __restrict__ u) {
    int idx = blockIdx.x * blockDim.x + threadIdx.x;
    u[idx]    = g_z[idx];
    g_mv[idx] = make_float2(0.f, 0.f);
}

// ---------------- global reduce (exact ops -> order-independent) ----------------
__global__ void reduce_kernel() {
    __shared__ float sv[256];
    __shared__ int   si[256];
    __shared__ float ss[256];
    const int tid = threadIdx.x;
    float best = 3.402823466e38f;
    int   bi   = 1 << 30;
    for (int j = tid; j < BROWS; j += 256) {
        float o = __ldcg(&g_sumexp[j]);
        if (o < best || (o == best && j < bi)) { best = o; bi = j; }
    }
    sv[tid] = best; si[tid] = bi;
    __syncthreads();
    for (int s = 128; s > 0; s >>= 1) {
        if (tid < s) {
            float ov = sv[tid + s]; int oi = si[tid + s];
            if (ov < sv[tid] || (ov == sv[tid] && oi < si[tid])) { sv[tid] = ov; si[tid] = oi; }
        }
        __syncthreads();
    }
    int istar = si[0];
    float pmax = 1.0f / sv[0];
    float s1 = 0.f;
    for (int j = tid; j < BROWS; j += 256) {
        float d = pmax - g_ptrg[j];
        s1 += (d > 0.f) ? 1.f : ((d < 0.f) ? -1.f : 0.f);
    }
    ss[tid] = s1;
    __syncthreads();
    for (int s = 128; s > 0; s >>= 1) {
        if (tid < s) ss[tid] += ss[tid + s];
        __syncthreads();
    }
    if (tid == 0) {
        g_istar      = istar;
        g_cstar      = __ldcg(&g_rowarg[istar]);
        g_rmaxstar   = __ldcg(&g_rowmax[istar]);
        g_sumexpstar = __ldcg(&g_sumexp[istar]);
        g_coef       = BETAc * 2048.0f * ss[0] * pmax;
    }
}

// ---------------- fused per-step kernel ----------------
// One block per row, 256 threads, 7 blocks/SM (1036 concurrent -> 1.98
// waves over 2048 blocks). Max/argmax/topu reductions are EXACT ops ->
// order-free -> warp-shuffle-first shape (2 syncs). The sumexp reduction
// keeps R1's exact (tid, tid+s) tree pairing (rounding-sensitive).
__global__ void __launch_bounds__(256, 7)
fused_kernel(float* __restrict__ u, int parity, float bc1, float bc2) {
    __shared__ float2 s_pair[BROWS];     // {topu[k], T[k]}
    __shared__ float smax[256];
    __shared__ int   sidx[256];
    __shared__ float stp[256];
    __shared__ float ssum[256];
    __shared__ unsigned int s_mask[32];

    const int i    = blockIdx.x;
    const int tid  = threadIdx.x;
    const int lane = tid & 31;
    const int warp = tid >> 5;
    const float* __restrict__ topuIn = g_topu2[parity];
    float* __restrict__ topuOut      = g_topu2[parity ^ 1];

    {   // stage paired {topu, T} (float4 loads, float2 interleaved stores)
        const float4* T4  = reinterpret_cast<const float4*>(g_T + ((size_t)i << 11));
        const float4* tu4 = reinterpret_cast<const float4*>(topuIn);
        float4 t0 = T4[tid];
        float4 u0 = tu4[tid];
        float4 t1 = T4[tid + 256];
        float4 u1 = tu4[tid + 256];
        int k0 = tid * 4;
        s_pair[k0 + 0] = make_float2(u0.x, t0.x);
        s_pair[k0 + 1] = make_float2(u0.y, t0.y);
        s_pair[k0 + 2] = make_float2(u0.z, t0.z);
        s_pair[k0 + 3] = make_float2(u0.w, t0.w);
        int k1 = (tid + 256) * 4;
        s_pair[k1 + 0] = make_float2(u1.x, t1.x);
        s_pair[k1 + 1] = make_float2(u1.y, t1.y);
        s_pair[k1 + 2] = make_float2(u1.z, t1.z);
        s_pair[k1 + 3] = make_float2(u1.w, t1.w);
        if (tid < 32) s_mask[tid] = g_maskw[tid];
    }
    const int   istar      = g_istar;      // written by previous reduce launch
    const int   cstar      = g_cstar;
    const float rmaxstar   = g_rmaxstar;
    const float sumexpstar = g_sumexpstar;
    const float coef       = g_coef;

    // hoist u + mv loads for all 4 column chunks (MLP)
    float  uv4[4];
    float2 mv4[4];
    int    cls_s[4], cls_e[4];
#pragma unroll
    for (int q = 0; q < 4; ++q) {
        int c = tid + q * 256;
        if (c < NCLS) {
            int idx = i * NCLS + c;
            uv4[q] = u[idx];
            mv4[q] = g_mv[idx];
            cls_s[q] = g_start[c];
            cls_e[q] = cls_s[q] + g_count[c];
        } else { uv4[q] = 0.f; mv4[q] = make_float2(0.f, 0.f); cls_s[q] = 0; cls_e[q] = 0; }
    }
    __syncthreads();

    // ---- gradient + Adam + u update; keep new u in va[] (R1 stats order) ----
    float va[4];
    int   nv = 0;
    float vmax = -3.402823466e38f;
    int   vidx = NCLS;
    float tmax = -1000.0f;
#pragma unroll
    for (int q = 0; q < 4; ++q) {
        int c = tid + q * 256;
        if (c < NCLS) {
            int idx = i * NCLS + c;
            float uv = uv4[q];
            float g = 0.f;
            for (int k = cls_s[q]; k < cls_e[q]; ++k) {
                float2 p = s_pair[k];
                float d = uv - p.x - p.y;
                g += (d > 0.f) ? 1.f : ((d < 0.f) ? -1.f : 0.f);
            }
            if (i == istar) {
                float p = expf(uv - rmaxstar) / sumexpstar;
                float ind = (c == cstar) ? 1.f : 0.f;
                g += coef * (ind - p);
            }
            float mv = B1c * mv4[q].x + (1.0f - B1c) * g;
            float vv = B2c * mv4[q].y + (1.0f - B2c) * g * g;
            g_mv[idx] = make_float2(mv, vv);
            float mhat = mv / bc1;
            float vhat = vv / bc2;
            float nu = uv - LRc * mhat / (sqrtf(vhat) + EPSc);
            u[idx] = nu;
            va[nv++] = nu;
            if (nu > vmax) { vmax = nu; vidx = c; }
            if ((s_mask[c >> 5] >> (c & 31)) & 1u) { if (nu > tmax) tmax = nu; }
        }
    }

    // ---- max/argmax/topu: EXACT ops -> warp-shuffle-first (order-free) ----
#pragma unroll
    for (int off = 16; off > 0; off >>= 1) {
        float ov = __shfl_down_sync(0xffffffffu, vmax, off);
        int   oi = __shfl_down_sync(0xffffffffu, vidx, off);
        float ot = __shfl_down_sync(0xffffffffu, tmax, off);
        if (ov > vmax || (ov == vmax && oi < vidx)) { vmax = ov; vidx = oi; }
        if (ot > tmax) tmax = ot;
    }
    if (lane == 0) { smax[warp] = vmax; sidx[warp] = vidx; stp[warp] = tmax; }
    __syncthreads();
    if (tid < 8) {
        float mv_ = smax[tid]; int mi_ = sidx[tid]; float tp_ = stp[tid];
        __syncwarp(0x000000ffu);
#pragma unroll
        for (int off = 4; off > 0; off >>= 1) {
            float ov = __shfl_down_sync(0x000000ffu, mv_, off);
            int   oi = __shfl_down_sync(0x000000ffu, mi_, off);
            float ot = __shfl_down_sync(0x000000ffu, tp_, off);
            if (ov > mv_ || (ov == mv_ && oi < mi_)) { mv_ = ov; mi_ = oi; }
            if (ot > tp_) tp_ = ot;
        }
        if (tid == 0) { smax[0] = mv_; sidx[0] = mi_; stp[0] = tp_; }
    }
    __syncthreads();
    const float rmax  = smax[0];
    const int   argr  = sidx[0];
    const float tmaxr = stp[0];

    // ---- sumexp: R1's exact tree pairing (rounding-sensitive, unchanged) ----
    float se = 0.f;
    for (int q = 0; q < nv; ++q) se += expf(va[q] - rmax);
    ssum[tid] = se;
    __syncthreads();
#pragma unroll
    for (int s = 128; s >= 32; s >>= 1) {
        if (tid < s) ssum[tid] += ssum[tid + s];
        __syncthreads();
    }
    if (tid < 32) {
        float sum_ = ssum[tid];
        __syncwarp(0xffffffffu);
#pragma unroll
        for (int off = 16; off > 0; off >>= 1)
            sum_ += __shfl_down_sync(0xffffffffu, sum_, off);
        if (tid == 0) {
            g_rowmax[i] = rmax;
            g_sumexp[i] = sum_;
            g_rowarg[i] = argr;
            topuOut[g_slotOfRow[i]] = tmaxr;
        }
    }
}

// ---------------- launch ----------------
extern "C" void kernel_launch(void* const* d_in, const int* in_sizes, int n_in,
                              void* d_out, int out_size) {
    const float* x = nullptr; const float* W = nullptr; const float* b = nullptr;
    for (int i = 0; i < n_in; ++i) {
        if (in_sizes[i] == BROWS * KDIM)      x = (const float*)d_in[i];
        else if (in_sizes[i] == KDIM * NCLS)  W = (const float*)d_in[i];
        else if (in_sizes[i] == NCLS)         b = (const float*)d_in[i];
    }
    float* u = (float*)d_out;

    dim3 gemm_grid((NCLS + 63) / 64, BROWS / 128);
    gemm_kernel<<<gemm_grid, 256>>>(x, W, b);          // our idx 0
    init_class_kernel<<<4, 256>>>();                   // idx 1
    statsz_kernel<<<BROWS, 256>>>();                   // idx 2

    // PROFILING PROBE: global launch #5 (harness issues 2 kernels first) is
    // what the fixed ncu capture (-s 5 -c 1) profiles. Runs the real fused
    // kernel on stale state; everything it writes (u, mv, stats, topu[0])
    // is recomputed below before the real loop, so the final output is
    // deterministic and unaffected.
    fused_kernel<<<BROWS, 256>>>(u, 1, 1.0f, 1.0f);    // idx 3  <-- PROFILED

    statsz_kernel<<<BROWS, 256>>>();                   // restore stats/y/ptrg
    mark_kernel<<<8, 256>>>();
    scan_kernel<<<1, 1>>>();
    scatter_kernel<<<8, 256>>>();
    maskw_kernel<<<1, 32>>>();
    topz_kernel<<<BROWS, 256>>>();                     // restores topu2[0]
    computeT_kernel<<<(BROWS * BROWS) / 256, 256>>>();
    init_u_kernel<<<(BROWS * NCLS) / 256, 256>>>(u);   // restores u, mv
    reduce_kernel<<<1, 256>>>();

    for (int t = 1; t <= NSTEPS; ++t) {
        float bc1 = (float)(1.0 - pow((double)B1c, (double)t));
        float bc2 = (float)(1.0 - pow((double)B2c, (double)t));
        fused_kernel<<<BROWS, 256>>>(u, (t - 1) & 1, bc1, bc2);
        reduce_kernel<<<1, 256>>>();
    }
}

// round 11
// speedup vs baseline: 1.0873x; 1.0873x over previous
#include <cuda_runtime.h>
#include <math.h>

#define BROWS 2048
#define NCLS  1000
#define KDIM  2048
#define NSTEPS 100

#define LRc   0.1f
#define B1c   0.9f
#define B2c   0.999f
#define EPSc  1e-8f
#define BETAc 5.0f
#define TAUc  6.0f
#define PI_F  3.14159274101257324f   // float(np.pi)

// ---------------- device scratch (static, no allocation) ----------------
__device__ float  g_z[BROWS * NCLS];
__device__ float2 g_mv[BROWS * NCLS];     // interleaved Adam m,v
__device__ float  g_T[BROWS * BROWS];     // l_trg, class-slot layout
__device__ float  g_topz[BROWS];
__device__ float  g_topu2[2][BROWS];      // double-buffered topu (slot order)
__device__ float  g_rowmax[BROWS];
__device__ float  g_sumexp[BROWS];
__device__ int    g_rowarg[BROWS];
__device__ float  g_ptrg[BROWS];
__device__ int    g_y[BROWS];
__device__ int    g_allowed[NCLS];
__device__ unsigned int g_maskw[32];      // allowed bitmask (1000 bits)
__device__ int    g_count[NCLS];
__device__ int    g_start[NCLS];
__device__ int    g_cursor[NCLS];
__device__ int    g_member[BROWS];        // row j, sorted by class
__device__ int    g_classOf[BROWS];       // class of slot k
__device__ int    g_slotOfRow[BROWS];     // inverse of g_member
__device__ int    g_istar;
__device__ int    g_cstar;
__device__ float  g_rmaxstar;
__device__ float  g_sumexpstar;
__device__ float  g_coef;

// ---------------- GEMM: z = x @ W + b (UNCHANGED from passing R9) ----------------
__global__ void __launch_bounds__(256)
gemm_kernel(const float* __restrict__ x,
            const float* __restrict__ W,
            const float* __restrict__ bias) {
    __shared__ float As[128][16];
    __shared__ float Bs[16][64];
    const int tid = threadIdx.x;
    const int tx = tid & 15;
    const int ty = tid >> 4;
    const int row0 = blockIdx.y * 128;
    const int col0 = blockIdx.x * 64;

    const int bk = tid >> 4;
    const int bn = (tid & 15) * 4;

    float acc[8][4];
#pragma unroll
    for (int i = 0; i < 8; ++i)
#pragma unroll
        for (int j = 0; j < 4; ++j) acc[i][j] = 0.f;

    for (int k0 = 0; k0 < KDIM; k0 += 16) {
#pragma unroll
        for (int q = 0; q < 2; ++q) {
            int idx = tid * 2 + q;
            int m  = idx >> 2;
            int kk = (idx & 3) * 4;
            float4 xa = *reinterpret_cast<const float4*>(
                &x[(size_t)(row0 + m) * KDIM + k0 + kk]);
            *reinterpret_cast<float4*>(&As[m][kk]) = xa;
        }
        {
            int n = col0 + bn;
            float4 wb;
            if (n + 3 < NCLS) {
                wb = *reinterpret_cast<const float4*>(&W[(size_t)(k0 + bk) * NCLS + n]);
            } else {
                wb = make_float4(0.f, 0.f, 0.f, 0.f);
            }
            *reinterpret_cast<float4*>(&Bs[bk][bn]) = wb;
        }
        __syncthreads();
#pragma unroll
        for (int kk = 0; kk < 16; ++kk) {
            float a[8];
#pragma unroll
            for (int i = 0; i < 8; ++i) a[i] = As[ty * 8 + i][kk];
            float4 bb = *reinterpret_cast<const float4*>(&Bs[kk][tx * 4]);
#pragma unroll
            for (int i = 0; i < 8; ++i) {
                acc[i][0] = fmaf(a[i], bb.x, acc[i][0]);
                acc[i][1] = fmaf(a[i], bb.y, acc[i][1]);
                acc[i][2] = fmaf(a[i], bb.z, acc[i][2]);
                acc[i][3] = fmaf(a[i], bb.w, acc[i][3]);
            }
        }
        __syncthreads();
    }
#pragma unroll
    for (int i = 0; i < 8; ++i) {
        int row = row0 + ty * 8 + i;
#pragma unroll
        for (int j = 0; j < 4; ++j) {
            int col = col0 + tx * 4 + j;
            if (col < NCLS) g_z[(size_t)row * NCLS + col] = acc[i][j] + bias[col];
        }
    }
}

// ---------------- setup kernels (identical arithmetic to R1) ----------------
__global__ void init_class_kernel() {
    int c = blockIdx.x * blockDim.x + threadIdx.x;
    if (c < NCLS) { g_allowed[c] = 1; g_count[c] = 0; g_cursor[c] = 0; }
}

__global__ void statsz_kernel() {
    int row = blockIdx.x;
    const float* a = g_z + (size_t)row * NCLS;
    int tid = threadIdx.x;

    float va[4];
    int   nv = 0;
    float vmax = -3.402823466e38f;
    int   vidx = NCLS;
    for (int c = tid; c < NCLS; c += 256) {
        float v = a[c];
        va[nv++] = v;
        if (v > vmax) { vmax = v; vidx = c; }
    }
    __shared__ float smax[256];
    __shared__ int   sidx[256];
    __shared__ float ssum[256];
    smax[tid] = vmax; sidx[tid] = vidx;
    __syncthreads();
    for (int s = 128; s > 0; s >>= 1) {
        if (tid < s) {
            float ov = smax[tid + s]; int oi = sidx[tid + s];
            if (ov > smax[tid] || (ov == smax[tid] && oi < sidx[tid])) { smax[tid] = ov; sidx[tid] = oi; }
        }
        __syncthreads();
    }
    float rmax = smax[0];
    float se = 0.f;
    for (int q = 0; q < nv; ++q) se += expf(va[q] - rmax);
    ssum[tid] = se;
    __syncthreads();
    for (int s = 128; s > 0; s >>= 1) {
        if (tid < s) ssum[tid] += ssum[tid + s];
        __syncthreads();
    }
    if (tid == 0) {
        g_rowmax[row] = rmax;
        g_sumexp[row] = ssum[0];
        g_rowarg[row] = sidx[0];
        g_y[row] = sidx[0];
        g_ptrg[row] = 1.0f / ssum[0];
    }
}

__global__ void mark_kernel() {
    int i = blockIdx.x * blockDim.x + threadIdx.x;
    if (i < BROWS) {
        int c = g_y[i];
        g_allowed[c] = 0;
        atomicAdd(&g_count[c], 1);
    }
}

__global__ void scan_kernel() {
    if (threadIdx.x == 0 && blockIdx.x == 0) {
        int s = 0;
        for (int c = 0; c < NCLS; ++c) { g_start[c] = s; s += g_count[c]; }
    }
}

__global__ void scatter_kernel() {
    int i = blockIdx.x * blockDim.x + threadIdx.x;
    if (i < BROWS) {
        int c = g_y[i];
        int pos = g_start[c] + atomicAdd(&g_cursor[c], 1);
        g_member[pos]    = i;
        g_classOf[pos]   = c;
        g_slotOfRow[i]   = pos;
    }
}

__global__ void maskw_kernel() {
    int w = threadIdx.x;   // 32 threads
    unsigned int m = 0;
    for (int b = 0; b < 32; ++b) {
        int c = w * 32 + b;
        if (c < NCLS && g_allowed[c]) m |= (1u << b);
    }
    g_maskw[w] = m;
}

// masked top over z + fill initial topu buffer 0 (slot order)
__global__ void topz_kernel() {
    int row = blockIdx.x;
    int tid = threadIdx.x;
    float tmax = -1000.0f;
    for (int c = tid; c < NCLS; c += 256) {
        if (g_allowed[c]) {
            float v = g_z[(size_t)row * NCLS + c];
            if (v > tmax) tmax = v;
        }
    }
    __shared__ float st[256];
    st[tid] = tmax;
    __syncthreads();
    for (int s = 128; s > 0; s >>= 1) {
        if (tid < s) { float o = st[tid + s]; if (o > st[tid]) st[tid] = o; }
        __syncthreads();
    }
    if (tid == 0) {
        g_topz[row] = st[0];
        g_topu2[0][g_slotOfRow[row]] = st[0];
    }
}

__global__ void computeT_kernel() {
    int idx = blockIdx.x * blockDim.x + threadIdx.x;
    int i = idx >> 11;
    int k = idx & 2047;
    int c = g_classOf[k];
    int j = g_member[k];
    float lorg = g_z[(size_t)i * NCLS + c] - g_topz[j];
    float latr = (floorf(lorg / TAUc) + 0.5f) * TAUc;
    float arg  = PI_F * (1.0f - 2.0f * (lorg - latr) / TAUc);
    g_T[idx] = lorg - TAUc * sinf(arg);
}

__global__ void init_u_kernel(float* __restrict__ u) {
    int idx = blockIdx.x * blockDim.x + threadIdx.x;
    u[idx]    = g_z[idx];
    g_mv[idx] = make_float2(0.f, 0.f);
}

// ---------------- global reduce (exact ops -> order-independent, any shape) ----
__global__ void reduce_kernel() {
    __shared__ float sv[1024];
    __shared__ int   si[1024];
    __shared__ float ss[1024];
    const int tid = threadIdx.x;
    float best = 3.402823466e38f;
    int   bi   = 1 << 30;
    for (int j = tid; j < BROWS; j += 1024) {
        float o = __ldcg(&g_sumexp[j]);
        if (o < best || (o == best && j < bi)) { best = o; bi = j; }
    }
    sv[tid] = best; si[tid] = bi;
    __syncthreads();
    for (int s = 512; s > 0; s >>= 1) {
        if (tid < s) {
            float ov = sv[tid + s]; int oi = si[tid + s];
            if (ov < sv[tid] || (ov == sv[tid] && oi < si[tid])) { sv[tid] = ov; si[tid] = oi; }
        }
        __syncthreads();
    }
    int istar = si[0];
    float pmax = 1.0f / sv[0];
    float s1 = 0.f;
    for (int j = tid; j < BROWS; j += 1024) {
        float d = pmax - g_ptrg[j];
        s1 += (d > 0.f) ? 1.f : ((d < 0.f) ? -1.f : 0.f);
    }
    ss[tid] = s1;
    __syncthreads();
    for (int s = 512; s > 0; s >>= 1) {
        if (tid < s) ss[tid] += ss[tid + s];
        __syncthreads();
    }
    if (tid == 0) {
        g_istar      = istar;
        g_cstar      = __ldcg(&g_rowarg[istar]);
        g_rmaxstar   = __ldcg(&g_rowmax[istar]);
        g_sumexpstar = __ldcg(&g_sumexp[istar]);
        g_coef       = BETAc * 2048.0f * ss[0] * pmax;
    }
}

// ---------------- fused per-step kernel (EXACT R9 version — best measured) ----
// One block per row, 256 threads, 6 blocks/SM (regs 40, occ 62% — measured
// faster than the 7-block/32-reg variant). Stats arithmetic replicates R1's
// stats_kernel bit-exactly (chunk order c = tid + 256q, same tree pairing;
// shuffle levels s=16..1 use identical (tid, tid+s) pairing). Inner gradient
// loop reads {topu[k], T[k]} as one float2 (same values, same op order).
__global__ void __launch_bounds__(256, 6)
fused_kernel(float* __restrict__ u, int parity, float bc1, float bc2) {
    __shared__ float2 s_pair[BROWS];     // {topu[k], T[k]}
    __shared__ float smax[256];
    __shared__ int   sidx[256];
    __shared__ float stp[256];
    __shared__ float ssum[256];
    __shared__ unsigned int s_mask[32];

    const int i   = blockIdx.x;
    const int tid = threadIdx.x;
    const float* __restrict__ topuIn = g_topu2[parity];
    float* __restrict__ topuOut      = g_topu2[parity ^ 1];

    {   // stage paired {topu, T} (float4 loads, float2 interleaved stores)
        const float4* T4  = reinterpret_cast<const float4*>(g_T + ((size_t)i << 11));
        const float4* tu4 = reinterpret_cast<const float4*>(topuIn);
        float4 t0 = T4[tid];
        float4 u0 = tu4[tid];
        float4 t1 = T4[tid + 256];
        float4 u1 = tu4[tid + 256];
        int k0 = tid * 4;
        s_pair[k0 + 0] = make_float2(u0.x, t0.x);
        s_pair[k0 + 1] = make_float2(u0.y, t0.y);
        s_pair[k0 + 2] = make_float2(u0.z, t0.z);
        s_pair[k0 + 3] = make_float2(u0.w, t0.w);
        int k1 = (tid + 256) * 4;
        s_pair[k1 + 0] = make_float2(u1.x, t1.x);
        s_pair[k1 + 1] = make_float2(u1.y, t1.y);
        s_pair[k1 + 2] = make_float2(u1.z, t1.z);
        s_pair[k1 + 3] = make_float2(u1.w, t1.w);
        if (tid < 32) s_mask[tid] = g_maskw[tid];
    }
    const int   istar      = g_istar;      // written by previous reduce launch
    const int   cstar      = g_cstar;
    const float rmaxstar   = g_rmaxstar;
    const float sumexpstar = g_sumexpstar;
    const float coef       = g_coef;

    // hoist u + mv loads for all 4 column chunks (MLP)
    float  uv4[4];
    float2 mv4[4];
    int    cls_s[4], cls_e[4];
#pragma unroll
    for (int q = 0; q < 4; ++q) {
        int c = tid + q * 256;
        if (c < NCLS) {
            int idx = i * NCLS + c;
            uv4[q] = u[idx];
            mv4[q] = g_mv[idx];
            cls_s[q] = g_start[c];
            cls_e[q] = cls_s[q] + g_count[c];
        } else { uv4[q] = 0.f; mv4[q] = make_float2(0.f, 0.f); cls_s[q] = 0; cls_e[q] = 0; }
    }
    __syncthreads();

    // ---- gradient + Adam + u update; keep new u in va[] (R1 stats order) ----
    float va[4];
    int   nv = 0;
    float vmax = -3.402823466e38f;
    int   vidx = NCLS;
    float tmax = -1000.0f;
#pragma unroll
    for (int q = 0; q < 4; ++q) {
        int c = tid + q * 256;
        if (c < NCLS) {
            int idx = i * NCLS + c;
            float uv = uv4[q];
            float g = 0.f;
            for (int k = cls_s[q]; k < cls_e[q]; ++k) {
                float2 p = s_pair[k];
                float d = uv - p.x - p.y;
                g += (d > 0.f) ? 1.f : ((d < 0.f) ? -1.f : 0.f);
            }
            if (i == istar) {
                float p = expf(uv - rmaxstar) / sumexpstar;
                float ind = (c == cstar) ? 1.f : 0.f;
                g += coef * (ind - p);
            }
            float mv = B1c * mv4[q].x + (1.0f - B1c) * g;
            float vv = B2c * mv4[q].y + (1.0f - B2c) * g * g;
            g_mv[idx] = make_float2(mv, vv);
            float mhat = mv / bc1;
            float vhat = vv / bc2;
            float nu = uv - LRc * mhat / (sqrtf(vhat) + EPSc);
            u[idx] = nu;
            va[nv++] = nu;
            if (nu > vmax) { vmax = nu; vidx = c; }
            if ((s_mask[c >> 5] >> (c & 31)) & 1u) { if (nu > tmax) tmax = nu; }
        }
    }

    // ---- stats trees: smem for s=128,64,32; shuffles for s=16..1 (same pairing) ----
    smax[tid] = vmax; sidx[tid] = vidx; stp[tid] = tmax;
    __syncthreads();
#pragma unroll
    for (int s = 128; s >= 32; s >>= 1) {
        if (tid < s) {
            float ov = smax[tid + s]; int oi = sidx[tid + s];
            if (ov > smax[tid] || (ov == smax[tid] && oi < sidx[tid])) { smax[tid] = ov; sidx[tid] = oi; }
            float ot = stp[tid + s];
            if (ot > stp[tid]) stp[tid] = ot;
        }
        __syncthreads();
    }
    float rmax, tmaxr; int argr;
    if (tid < 32) {
        float mv_ = smax[tid]; int mi_ = sidx[tid]; float tp_ = stp[tid];
        __syncwarp(0xffffffffu);
#pragma unroll
        for (int off = 16; off > 0; off >>= 1) {
            float ov = __shfl_down_sync(0xffffffffu, mv_, off);
            int   oi = __shfl_down_sync(0xffffffffu, mi_, off);
            float ot = __shfl_down_sync(0xffffffffu, tp_, off);
            if (ov > mv_ || (ov == mv_ && oi < mi_)) { mv_ = ov; mi_ = oi; }
            if (ot > tp_) tp_ = ot;
        }
        if (tid == 0) { smax[0] = mv_; sidx[0] = mi_; stp[0] = tp_; }
    }
    __syncthreads();
    rmax = smax[0]; argr = sidx[0]; tmaxr = stp[0];

    float se = 0.f;
    for (int q = 0; q < nv; ++q) se += expf(va[q] - rmax);
    ssum[tid] = se;
    __syncthreads();
#pragma unroll
    for (int s = 128; s >= 32; s >>= 1) {
        if (tid < s) ssum[tid] += ssum[tid + s];
        __syncthreads();
    }
    if (tid < 32) {
        float sum_ = ssum[tid];
        __syncwarp(0xffffffffu);
#pragma unroll
        for (int off = 16; off > 0; off >>= 1)
            sum_ += __shfl_down_sync(0xffffffffu, sum_, off);
        if (tid == 0) {
            g_rowmax[i] = rmax;
            g_sumexp[i] = sum_;
            g_rowarg[i] = argr;
            topuOut[g_slotOfRow[i]] = tmaxr;
        }
    }
}

// ---------------- launch ----------------
extern "C" void kernel_launch(void* const* d_in, const int* in_sizes, int n_in,
                              void* d_out, int out_size) {
    const float* x = nullptr; const float* W = nullptr; const float* b = nullptr;
    for (int i = 0; i < n_in; ++i) {
        if (in_sizes[i] == BROWS * KDIM)      x = (const float*)d_in[i];
        else if (in_sizes[i] == KDIM * NCLS)  W = (const float*)d_in[i];
        else if (in_sizes[i] == NCLS)         b = (const float*)d_in[i];
    }
    float* u = (float*)d_out;

    dim3 gemm_grid((NCLS + 63) / 64, BROWS / 128);
    gemm_kernel<<<gemm_grid, 256>>>(x, W, b);

    init_class_kernel<<<4, 256>>>();
    statsz_kernel<<<BROWS, 256>>>();
    mark_kernel<<<8, 256>>>();
    scan_kernel<<<1, 1>>>();
    scatter_kernel<<<8, 256>>>();
    maskw_kernel<<<1, 32>>>();
    topz_kernel<<<BROWS, 256>>>();
    computeT_kernel<<<(BROWS * BROWS) / 256, 256>>>();
    init_u_kernel<<<(BROWS * NCLS) / 256, 256>>>(u);
    reduce_kernel<<<1, 1024>>>();

    for (int t = 1; t <= NSTEPS; ++t) {
        float bc1 = (float)(1.0 - pow((double)B1c, (double)t));
        float bc2 = (float)(1.0 - pow((double)B2c, (double)t));
        fused_kernel<<<BROWS, 256>>>(u, (t - 1) & 1, bc1, bc2);
        reduce_kernel<<<1, 1024>>>();
    }
}